// round 3
// baseline (speedup 1.0000x reference)
#include <cuda_runtime.h>

// Problem constants
#define BB 256
#define TT 1024
#define IDIM 2
#define HH 128
#define LL 4

// Ping-pong hidden-sequence scratch (device globals: allocation-free).
__device__ float g_h0[BB * TT * HH];
__device__ float g_h1[BB * TT * HH];

// Packed f32x2 FMA (Blackwell dual-fp32 path; only reachable via PTX).
__device__ __forceinline__ void ffma2(unsigned long long& acc,
                                      unsigned long long a,
                                      unsigned long long b) {
    asm("fma.rn.f32x2 %0, %1, %2, %0;" : "+l"(acc) : "l"(a), "l"(b));
}
__device__ __forceinline__ unsigned long long add2(unsigned long long a,
                                                   unsigned long long b) {
    unsigned long long d;
    asm("add.rn.f32x2 %0, %1, %2;" : "=l"(d) : "l"(a), "l"(b));
    return d;
}

// One RNN layer scan. Each CTA owns 2 batch rows for all T steps.
// Thread (j = tid&127, s = tid>>7) computes output unit j, k-chunk [s*64, s*64+64).
// Weights live in registers as pre-packed (w_k, w_{k+1}) f32x2 pairs.
__global__ void __launch_bounds__(256, 1)
rnn_scan(const float* __restrict__ in, float* __restrict__ out,
         const float* __restrict__ Wih, const float* __restrict__ Whh,
         const float* __restrict__ bih, const float* __restrict__ bhh,
         int layer) {
    __shared__ __align__(16) float h_s[2][HH];    // h(t-1), layout [row][k]
    __shared__ __align__(16) float in_s[2][HH];   // layer input at step t
    __shared__ __align__(16) ulonglong2 ps[HH];   // s=1 partial sums (r0, r1)
    __shared__ __align__(16) float x_s[4];        // layer-0 raw x staging

    const int tid = threadIdx.x;
    const int j = tid & 127;
    const int s = tid >> 7;
    const int b0 = blockIdx.x * 2;
    const int rr = tid >> 7;       // row index for staging (0/1)
    const int kk = tid & 127;      // k index for staging

    // ---- load weights into registers (packed k-pairs) ----
    unsigned long long whh[32];
    unsigned long long wih[32];
    {
        const unsigned long long* p =
            (const unsigned long long*)(Whh + j * HH + s * 64);
#pragma unroll
        for (int i = 0; i < 32; i++) whh[i] = p[i];
    }
    float wi0 = 0.f, wi1 = 0.f;
    if (layer > 0) {
        const unsigned long long* p =
            (const unsigned long long*)(Wih + j * HH + s * 64);
#pragma unroll
        for (int i = 0; i < 32; i++) wih[i] = p[i];
    } else {
        wi0 = Wih[j * 2 + 0];
        wi1 = Wih[j * 2 + 1];
#pragma unroll
        for (int i = 0; i < 32; i++) wih[i] = 0ULL;
    }
    const float bias = bih[j] + bhh[j];

    // ---- init: h(-1) = 0, stage input for t=0 ----
    if (s == 0) { h_s[0][j] = 0.f; h_s[1][j] = 0.f; }
    if (layer > 0) {
        in_s[rr][kk] = in[(b0 + rr) * (TT * HH) + 0 * HH + kk];
    } else if (tid < 4) {
        x_s[tid] = in[(b0 + (tid >> 1)) * (TT * IDIM) + 0 * IDIM + (tid & 1)];
    }
    __syncthreads();

    for (int t = 0; t < TT; ++t) {
        // ---- prefetch input for step t+1 (no dependency on recurrence) ----
        float nxt = 0.f, xnxt = 0.f;
        if (layer > 0) {
            if (t + 1 < TT)
                nxt = in[(b0 + rr) * (TT * HH) + (t + 1) * HH + kk];
        } else {
            if (tid < 4 && t + 1 < TT)
                xnxt = in[(b0 + (tid >> 1)) * (TT * IDIM) + (t + 1) * IDIM +
                          (tid & 1)];
        }

        unsigned long long acc0 = 0ULL, acc1 = 0ULL;  // f32x2 (+0, +0)

        // ---- recurrent matvec: acc += Whh[j, k-chunk] . h(t-1) ----
        {
            const ulonglong2* hp0 = (const ulonglong2*)(&h_s[0][s * 64]);
            const ulonglong2* hp1 = (const ulonglong2*)(&h_s[1][s * 64]);
#pragma unroll
            for (int q = 0; q < 16; q++) {
                ulonglong2 v0 = hp0[q];  // LDS.128 broadcast
                ulonglong2 v1 = hp1[q];
                ffma2(acc0, v0.x, whh[2 * q]);
                ffma2(acc0, v0.y, whh[2 * q + 1]);
                ffma2(acc1, v1.x, whh[2 * q]);
                ffma2(acc1, v1.y, whh[2 * q + 1]);
            }
        }

        // ---- fused input projection ----
        float xp0 = 0.f, xp1 = 0.f;
        if (layer > 0) {
            const ulonglong2* ip0 = (const ulonglong2*)(&in_s[0][s * 64]);
            const ulonglong2* ip1 = (const ulonglong2*)(&in_s[1][s * 64]);
#pragma unroll
            for (int q = 0; q < 16; q++) {
                ulonglong2 v0 = ip0[q];
                ulonglong2 v1 = ip1[q];
                ffma2(acc0, v0.x, wih[2 * q]);
                ffma2(acc0, v0.y, wih[2 * q + 1]);
                ffma2(acc1, v1.x, wih[2 * q]);
                ffma2(acc1, v1.y, wih[2 * q + 1]);
            }
        } else if (s == 0) {
            // read x(t) BEFORE the barrier (it is overwritten after it)
            float4 xv = *(const float4*)x_s;
            xp0 = xv.x * wi0 + xv.y * wi1;
            xp1 = xv.z * wi0 + xv.w * wi1;
        }

        if (s == 1) ps[j] = make_ulonglong2(acc0, acc1);
        __syncthreads();

        // ---- reduce halves, bias, ReLU, publish h(t) ----
        if (s == 0) {
            ulonglong2 p = ps[j];
            unsigned long long a0 = add2(acc0, p.x);
            unsigned long long a1 = add2(acc1, p.y);
            float2 f0 = *(float2*)&a0;
            float2 f1 = *(float2*)&a1;
            float h0 = fmaxf(f0.x + f0.y + xp0 + bias, 0.f);
            float h1 = fmaxf(f1.x + f1.y + xp1 + bias, 0.f);
            h_s[0][j] = h0;
            h_s[1][j] = h1;
            int base = b0 * (TT * HH) + t * HH + j;
            out[base] = h0;
            out[base + TT * HH] = h1;
        }
        // stage input for t+1 (reads of in_s(t)/x_s(t) completed before bar)
        if (layer > 0) {
            if (t + 1 < TT) in_s[rr][kk] = nxt;
        } else if (tid < 4 && t + 1 < TT) {
            x_s[tid] = xnxt;
        }
        __syncthreads();
    }
}

// FC on last timestep: out[b] = h[b, T-1, :] . fc_w + fc_b
__global__ void fc_kernel(const float* __restrict__ h,
                          const float* __restrict__ fcw,
                          const float* __restrict__ fcb,
                          float* __restrict__ out) {
    int b = blockIdx.x;
    int k = threadIdx.x;
    float v = h[b * (TT * HH) + (TT - 1) * HH + k] * fcw[k];
#pragma unroll
    for (int o = 16; o > 0; o >>= 1)
        v += __shfl_down_sync(0xffffffffu, v, o);
    __shared__ float sred[4];
    if ((k & 31) == 0) sred[k >> 5] = v;
    __syncthreads();
    if (k == 0) out[b] = sred[0] + sred[1] + sred[2] + sred[3] + fcb[0];
}

extern "C" void kernel_launch(void* const* d_in, const int* in_sizes, int n_in,
                              void* d_out, int out_size) {
    const float* x    = (const float*)d_in[0];  // [B,T,I]
    const float* Wih0 = (const float*)d_in[1];  // [H,I]
    const float* WihL = (const float*)d_in[2];  // [L-1,H,H]
    const float* Whh  = (const float*)d_in[3];  // [L,H,H]
    const float* bih  = (const float*)d_in[4];  // [L,H]
    const float* bhh  = (const float*)d_in[5];  // [L,H]
    const float* fcw  = (const float*)d_in[6];  // [C,H]
    const float* fcb  = (const float*)d_in[7];  // [C]
    float* out = (float*)d_out;                 // [B,C] = [256,1]

    float *h0, *h1;
    cudaGetSymbolAddress((void**)&h0, g_h0);
    cudaGetSymbolAddress((void**)&h1, g_h1);

    const int HW = HH * HH;
    // layer 0: x -> h0
    rnn_scan<<<BB / 2, 256>>>(x, h0, Wih0, Whh + 0 * HW, bih + 0 * HH,
                              bhh + 0 * HH, 0);
    // layer 1: h0 -> h1
    rnn_scan<<<BB / 2, 256>>>(h0, h1, WihL + 0 * HW, Whh + 1 * HW, bih + 1 * HH,
                              bhh + 1 * HH, 1);
    // layer 2: h1 -> h0
    rnn_scan<<<BB / 2, 256>>>(h1, h0, WihL + 1 * HW, Whh + 2 * HW, bih + 2 * HH,
                              bhh + 2 * HH, 2);
    // layer 3: h0 -> h1
    rnn_scan<<<BB / 2, 256>>>(h0, h1, WihL + 2 * HW, Whh + 3 * HW, bih + 3 * HH,
                              bhh + 3 * HH, 3);
    // fc on last timestep
    fc_kernel<<<BB, HH>>>(h1, fcw, fcb, out);
}